// round 1
// baseline (speedup 1.0000x reference)
#include <cuda_runtime.h>
#include <cuda_bf16.h>
#include <cstdint>

#define B_ 64
#define S_ 512
#define D_ 512
#define NCHUNK 16   // 512 / 32
#define TMK 32      // K-chunk (bf16 elems)
#define SROW 40     // smem row stride in bf16 (32 data + 8 pad -> 80B, conflict-free ldmatrix)

// ---- scratch (static device allocations; no cudaMalloc allowed) ----
__device__ __nv_bfloat16 g_e1[B_ * S_ * D_];   // 32 MB normalized bf16
__device__ __nv_bfloat16 g_e2[B_ * S_ * D_];   // 32 MB
__device__ unsigned g_rowmax[B_ * S_];
__device__ unsigned g_colmax[B_ * S_];
__device__ int g_n1[B_];
__device__ int g_n2[B_];

// order-preserving float<->uint transform so atomicMax(unsigned) == float max
__device__ __forceinline__ unsigned enc_f(float f) {
    unsigned u = __float_as_uint(f);
    return (u & 0x80000000u) ? ~u : (u | 0x80000000u);
}
__device__ __forceinline__ float dec_f(unsigned u) {
    return (u & 0x80000000u) ? __uint_as_float(u ^ 0x80000000u) : __uint_as_float(~u);
}

// ---- kernel 1: mask sums + init max buffers ----
__global__ void prep_kernel(const int* __restrict__ m1, const int* __restrict__ m2) {
    int b = blockIdx.x, t = threadIdx.x;
    int s1 = 0, s2 = 0;
    for (int i = t; i < S_; i += 256) {
        s1 += m1[b * S_ + i];
        s2 += m2[b * S_ + i];
        g_rowmax[b * S_ + i] = 0u;   // enc-min
        g_colmax[b * S_ + i] = 0u;
    }
#pragma unroll
    for (int o = 16; o; o >>= 1) {
        s1 += __shfl_xor_sync(0xffffffffu, s1, o);
        s2 += __shfl_xor_sync(0xffffffffu, s2, o);
    }
    __shared__ int r1[8], r2[8];
    if ((t & 31) == 0) { r1[t >> 5] = s1; r2[t >> 5] = s2; }
    __syncthreads();
    if (t == 0) {
        int a = 0, c = 0;
#pragma unroll
        for (int w = 0; w < 8; w++) { a += r1[w]; c += r2[w]; }
        g_n1[b] = a;
        g_n2[b] = c;
    }
}

// ---- kernel 2: L2-normalize rows, write bf16 scratch (1 warp per row) ----
__global__ void norm_kernel(const float* __restrict__ in1, const float* __restrict__ in2) {
    int row = blockIdx.x * 8 + (threadIdx.x >> 5);
    int lane = threadIdx.x & 31;
    const float* src;
    __nv_bfloat16* dst;
    if (row < B_ * S_) {
        src = in1 + (size_t)row * D_;
        dst = g_e1 + (size_t)row * D_;
    } else {
        int r = row - B_ * S_;
        src = in2 + (size_t)r * D_;
        dst = g_e2 + (size_t)r * D_;
    }
    float4 v[4];
    float ss = 0.f;
#pragma unroll
    for (int q = 0; q < 4; q++) {
        v[q] = ((const float4*)src)[lane + q * 32];
        ss += v[q].x * v[q].x + v[q].y * v[q].y + v[q].z * v[q].z + v[q].w * v[q].w;
    }
#pragma unroll
    for (int o = 16; o; o >>= 1) ss += __shfl_xor_sync(0xffffffffu, ss, o);
    float inv = 1.0f / fmaxf(sqrtf(ss), 1e-8f);
#pragma unroll
    for (int q = 0; q < 4; q++) {
        __nv_bfloat162 h0 = __floats2bfloat162_rn(v[q].x * inv, v[q].y * inv);
        __nv_bfloat162 h1 = __floats2bfloat162_rn(v[q].z * inv, v[q].w * inv);
        ((__nv_bfloat162*)dst)[(lane + q * 32) * 2 + 0] = h0;
        ((__nv_bfloat162*)dst)[(lane + q * 32) * 2 + 1] = h1;
    }
}

// ---- kernel 3: 128x128-tile bf16 mma.sync GEMM with fused masked row/col max ----
__global__ void __launch_bounds__(256, 2) sim_kernel() {
    int b = blockIdx.z;
    int n1 = g_n1[b], n2 = g_n2[b];
    int i0 = blockIdx.y * 128, j0 = blockIdx.x * 128;
    if (i0 >= n1 || j0 >= n2) return;   // prefix-mask tile skipping

    __shared__ __align__(16) __nv_bfloat16 As[2][128 * SROW];
    __shared__ __align__(16) __nv_bfloat16 Bs[2][128 * SROW];

    int tid = threadIdx.x, lane = tid & 31, warp = tid >> 5;
    int wm = warp >> 2, wn = warp & 3;   // 2 x 4 warp grid, warp tile 64x32

    const __nv_bfloat16* Ag = g_e1 + ((size_t)b * S_ + i0) * D_;
    const __nv_bfloat16* Bg = g_e2 + ((size_t)b * S_ + j0) * D_;

    float acc[4][4][4];
#pragma unroll
    for (int a = 0; a < 4; a++)
#pragma unroll
        for (int c = 0; c < 4; c++)
#pragma unroll
            for (int d = 0; d < 4; d++) acc[a][c][d] = 0.f;

    auto issue = [&](int kc, int buf) {
        int k0 = kc * TMK;
#pragma unroll
        for (int r = 0; r < 2; r++) {
            int idx = tid + r * 256;
            int row = idx >> 2, seg = idx & 3;
            {
                const void* gp = Ag + (size_t)row * D_ + k0 + seg * 8;
                uint32_t sa = (uint32_t)__cvta_generic_to_shared(&As[buf][row * SROW + seg * 8]);
                asm volatile("cp.async.cg.shared.global [%0], [%1], 16;\n" ::"r"(sa), "l"(gp));
            }
            {
                const void* gp = Bg + (size_t)row * D_ + k0 + seg * 8;
                uint32_t sb = (uint32_t)__cvta_generic_to_shared(&Bs[buf][row * SROW + seg * 8]);
                asm volatile("cp.async.cg.shared.global [%0], [%1], 16;\n" ::"r"(sb), "l"(gp));
            }
        }
        asm volatile("cp.async.commit_group;\n");
    };

    issue(0, 0);
#pragma unroll 1
    for (int kc = 0; kc < NCHUNK; kc++) {
        int buf = kc & 1;
        if (kc + 1 < NCHUNK) {
            issue(kc + 1, buf ^ 1);
            asm volatile("cp.async.wait_group 1;\n");
        } else {
            asm volatile("cp.async.wait_group 0;\n");
        }
        __syncthreads();

#pragma unroll
        for (int ks = 0; ks < 2; ks++) {
            uint32_t af[4][4];
#pragma unroll
            for (int tm = 0; tm < 4; tm++) {
                int row = wm * 64 + tm * 16 + (lane & 15);
                int col = ks * 16 + (lane >> 4) * 8;
                uint32_t addr = (uint32_t)__cvta_generic_to_shared(&As[buf][row * SROW + col]);
                asm volatile("ldmatrix.sync.aligned.m8n8.x4.shared.b16 {%0,%1,%2,%3},[%4];\n"
                             : "=r"(af[tm][0]), "=r"(af[tm][1]), "=r"(af[tm][2]), "=r"(af[tm][3])
                             : "r"(addr));
            }
            uint32_t bfr[4][2];
#pragma unroll
            for (int tn = 0; tn < 4; tn++) {
                int l = lane & 15;
                int rowb = wn * 32 + tn * 8 + (l & 7);
                int colb = ks * 16 + (l >> 3) * 8;
                uint32_t addr = (uint32_t)__cvta_generic_to_shared(&Bs[buf][rowb * SROW + colb]);
                asm volatile("ldmatrix.sync.aligned.m8n8.x2.shared.b16 {%0,%1},[%2];\n"
                             : "=r"(bfr[tn][0]), "=r"(bfr[tn][1])
                             : "r"(addr));
            }
#pragma unroll
            for (int tm = 0; tm < 4; tm++)
#pragma unroll
                for (int tn = 0; tn < 4; tn++)
                    asm volatile(
                        "mma.sync.aligned.m16n8k16.row.col.f32.bf16.bf16.f32 "
                        "{%0,%1,%2,%3},{%4,%5,%6,%7},{%8,%9},{%0,%1,%2,%3};\n"
                        : "+f"(acc[tm][tn][0]), "+f"(acc[tm][tn][1]),
                          "+f"(acc[tm][tn][2]), "+f"(acc[tm][tn][3])
                        : "r"(af[tm][0]), "r"(af[tm][1]), "r"(af[tm][2]), "r"(af[tm][3]),
                          "r"(bfr[tn][0]), "r"(bfr[tn][1]));
        }
        __syncthreads();
    }

    // ---- fused masked reductions ----
    // C frag layout (m16n8): c[rr*2+cc] at row = lane/4 + rr*8, col = (lane%4)*2 + cc
    const float NEGINF = -3.0e38f;

    // row max over valid j, reduce across quad (lane%4), atomicMax per row
#pragma unroll
    for (int tm = 0; tm < 4; tm++) {
#pragma unroll
        for (int rr = 0; rr < 2; rr++) {
            float v = NEGINF;
#pragma unroll
            for (int tn = 0; tn < 4; tn++) {
#pragma unroll
                for (int cc = 0; cc < 2; cc++) {
                    int j = j0 + wn * 32 + tn * 8 + (lane & 3) * 2 + cc;
                    if (j < n2) v = fmaxf(v, acc[tm][tn][rr * 2 + cc]);
                }
            }
            v = fmaxf(v, __shfl_xor_sync(0xffffffffu, v, 1));
            v = fmaxf(v, __shfl_xor_sync(0xffffffffu, v, 2));
            if ((lane & 3) == 0) {
                int i = i0 + wm * 64 + tm * 16 + (lane >> 2) + rr * 8;
                if (i < n1) atomicMax(&g_rowmax[b * S_ + i], enc_f(v));
            }
        }
    }

    // col max over valid i, reduce across lane/4 groups, atomicMax per col
#pragma unroll
    for (int tn = 0; tn < 4; tn++) {
#pragma unroll
        for (int cc = 0; cc < 2; cc++) {
            float v = NEGINF;
#pragma unroll
            for (int tm = 0; tm < 4; tm++) {
#pragma unroll
                for (int rr = 0; rr < 2; rr++) {
                    int i = i0 + wm * 64 + tm * 16 + (lane >> 2) + rr * 8;
                    if (i < n1) v = fmaxf(v, acc[tm][tn][rr * 2 + cc]);
                }
            }
            v = fmaxf(v, __shfl_xor_sync(0xffffffffu, v, 4));
            v = fmaxf(v, __shfl_xor_sync(0xffffffffu, v, 8));
            v = fmaxf(v, __shfl_xor_sync(0xffffffffu, v, 16));
            if (lane < 4) {
                int j = j0 + wn * 32 + tn * 8 + lane * 2 + cc;
                if (j < n2) atomicMax(&g_colmax[b * S_ + j], enc_f(v));
            }
        }
    }
}

// ---- kernel 4: final per-batch reduce ----
__global__ void final_kernel(float* __restrict__ out) {
    int b = blockIdx.x, t = threadIdx.x;
    int n1 = g_n1[b], n2 = g_n2[b];
    float s = 0.f;
    for (int i = t; i < n1; i += 256) s += dec_f(g_rowmax[b * S_ + i]);
    for (int j = t; j < n2; j += 256) s += dec_f(g_colmax[b * S_ + j]);
#pragma unroll
    for (int o = 16; o; o >>= 1) s += __shfl_xor_sync(0xffffffffu, s, o);
    __shared__ float red[8];
    if ((t & 31) == 0) red[t >> 5] = s;
    __syncthreads();
    if (t == 0) {
        float tot = 0.f;
#pragma unroll
        for (int w = 0; w < 8; w++) tot += red[w];
        out[b] = tot / (float)(n1 + n2);
    }
}

extern "C" void kernel_launch(void* const* d_in, const int* in_sizes, int n_in,
                              void* d_out, int out_size) {
    (void)in_sizes; (void)n_in; (void)out_size;
    const float* e1 = (const float*)d_in[0];
    const float* e2 = (const float*)d_in[1];
    const int* m1 = (const int*)d_in[2];
    const int* m2 = (const int*)d_in[3];

    prep_kernel<<<B_, 256>>>(m1, m2);
    norm_kernel<<<(2 * B_ * S_) / 8, 256>>>(e1, e2);
    sim_kernel<<<dim3(4, 4, B_), 256>>>();
    final_kernel<<<B_, 256>>>((float*)d_out);
}